// round 16
// baseline (speedup 1.0000x reference)
#include <cuda_runtime.h>
#include <cuda_fp16.h>
#include <cstdint>
#include <cstddef>

#define BB   2
#define TT   2048
#define DD   1024
#define HH   16
#define HDD  64
#define FFD  4096
#define MT   (BB*TT)
#define QS   (3*DD)          // fused qkv row stride (fp16)

// ---------------------------------------------------------------------------
// Scratch
// ---------------------------------------------------------------------------
__device__ __half g_h  [MT*DD];
__device__ __half g_qkv[MT*QS];
__device__ __half g_ao [MT*DD];
__device__ float  g_tmp[MT*DD];
__device__ __half g_y  [MT*DD];
__device__ __half g_mid[MT*FFD];
__device__ __half g_w  [12*1024*1024]; // fp16 T: wqkvT[3072][1024] | woT | w1T | w2T

#define WQKV_OFF 0
#define WO_OFF (3*1024*1024)
#define W1_OFF (4*1024*1024)
#define W2_OFF (8*1024*1024)

// ---------------------------------------------------------------------------
// Helpers
// ---------------------------------------------------------------------------
__device__ __forceinline__ uint32_t smaddr(const void* p) {
    return (uint32_t)__cvta_generic_to_shared(p);
}
#define CP16(dst, src) asm volatile("cp.async.cg.shared.global [%0], [%1], 16;\n" :: "r"(dst), "l"(src))
#define CP_COMMIT()    asm volatile("cp.async.commit_group;\n")

// fp16 m16n8k16
__device__ __forceinline__ void mma16(float* d, const uint32_t* a, const uint32_t* b) {
    asm volatile(
        "mma.sync.aligned.m16n8k16.row.col.f32.f16.f16.f32 "
        "{%0,%1,%2,%3}, {%4,%5,%6,%7}, {%8,%9}, {%0,%1,%2,%3};\n"
        : "+f"(d[0]), "+f"(d[1]), "+f"(d[2]), "+f"(d[3])
        : "r"(a[0]), "r"(a[1]), "r"(a[2]), "r"(a[3]), "r"(b[0]), "r"(b[1]));
}

__device__ __forceinline__ uint32_t packh2(float x, float y) {
    __half2 t = __floats2half2_rn(x, y);
    return *(uint32_t*)&t;
}

#define LDSM4(r0, r1, r2, r3, addr) \
    asm volatile("ldmatrix.sync.aligned.m8n8.x4.shared.b16 {%0,%1,%2,%3}, [%4];" \
                 : "=r"(r0), "=r"(r1), "=r"(r2), "=r"(r3) : "r"(addr))
#define LDSM4T(r0, r1, r2, r3, addr) \
    asm volatile("ldmatrix.sync.aligned.m8n8.x4.trans.shared.b16 {%0,%1,%2,%3}, [%4];" \
                 : "=r"(r0), "=r"(r1), "=r"(r2), "=r"(r3) : "r"(addr))

// ---------------------------------------------------------------------------
// Pack weights -> fp16, TRANSPOSED to [N][K] row-major.
// ---------------------------------------------------------------------------
__global__ void __launch_bounds__(256) packT_kernel(
    const float* __restrict__ wq, const float* __restrict__ wk,
    const float* __restrict__ wv, const float* __restrict__ wo,
    const float* __restrict__ w1, const float* __restrict__ w2,
    __half* __restrict__ out)
{
    __shared__ float tile[32][33];
    int t = blockIdx.x;
    const float* src; __half* dst;
    int srcN, dstK, n0, k0, scol;
    if (t < 3072) {
        int nt = t >> 5, kt = t & 31;
        n0 = nt * 32; k0 = kt * 32;
        int sel = n0 >> 10;
        src = sel == 0 ? wq : (sel == 1 ? wk : wv);
        srcN = 1024; scol = n0 & 1023;
        dst = out + WQKV_OFF; dstK = 1024;
    } else if (t < 4096) {
        int u = t - 3072;
        int nt = u >> 5, kt = u & 31;
        n0 = nt * 32; k0 = kt * 32;
        src = wo; srcN = 1024; scol = n0;
        dst = out + WO_OFF; dstK = 1024;
    } else if (t < 8192) {
        int u = t - 4096;
        int nt = u >> 5, kt = u & 31;
        n0 = nt * 32; k0 = kt * 32;
        src = w1; srcN = 4096; scol = n0;
        dst = out + W1_OFF; dstK = 1024;
    } else {
        int u = t - 8192;
        int nt = u >> 7, kt = u & 127;
        n0 = nt * 32; k0 = kt * 32;
        src = w2; srcN = 1024; scol = n0;
        dst = out + W2_OFF; dstK = 4096;
    }
    int tx = threadIdx.x & 31, ty = threadIdx.x >> 5;
#pragma unroll
    for (int i = 0; i < 4; i++)
        tile[ty + i * 8][tx] = src[(size_t)(k0 + ty + i * 8) * srcN + scol + tx];
    __syncthreads();
#pragma unroll
    for (int i = 0; i < 4; i++)
        dst[(size_t)(n0 + ty + i * 8) * dstK + k0 + tx] = __float2half(tile[tx][ty + i * 8]);
}

// ---------------------------------------------------------------------------
// RMSNorm
// ---------------------------------------------------------------------------
template <typename AT, typename OT>
__global__ void __launch_bounds__(256) rmsnorm_kernel(
    const AT* __restrict__ a, const float* __restrict__ b,
    const float* __restrict__ w, OT* __restrict__ out)
{
    int row = blockIdx.x;
    size_t base = (size_t)row * DD;
    float v[4];
    float ss = 0.f;
#pragma unroll
    for (int t = 0; t < 4; t++) {
        int c = threadIdx.x + t * 256;
        float x = (float)a[base + c];
        if (b) x += b[base + c];
        v[t] = x;
        ss += x * x;
    }
    __shared__ float red[8];
#pragma unroll
    for (int o = 16; o; o >>= 1) ss += __shfl_xor_sync(0xffffffffu, ss, o);
    if ((threadIdx.x & 31) == 0) red[threadIdx.x >> 5] = ss;
    __syncthreads();
    if (threadIdx.x == 0) {
        float tot = 0.f;
#pragma unroll
        for (int i = 0; i < 8; i++) tot += red[i];
        red[0] = tot;
    }
    __syncthreads();
    float scale = rsqrtf(red[0] * (1.0f / DD) + 1e-6f);
#pragma unroll
    for (int t = 0; t < 4; t++) {
        int c = threadIdx.x + t * 256;
        out[base + c] = (OT)(v[t] * scale * w[c]);
    }
}

// ---------------------------------------------------------------------------
// FP16 GEMM: BM=BN=128, BK=32, 128 threads = 4 warps x (64x64 tile),
// m16n8k16 + LDSM, 3-stage cp.async, ONE sync per chunk, 2 CTAs/SM.
// Per warp-chunk: 16 LDSM + 64 HMMA (vs 12/32 in the 8-warp version).
// ---------------------------------------------------------------------------
template <int EPI, typename OT>
__global__ void __launch_bounds__(128, 2) hgemm_kernel(
    const __half* __restrict__ A, const __half* __restrict__ Bt,
    OT* __restrict__ C, int M, int N, int K)
{
    __shared__ __half As[3][128 * 40];   // 10240B/stage
    __shared__ __half Bs[3][128 * 40];

    int tid = threadIdx.x;
    int warp = tid >> 5, lane = tid & 31;
    int g = lane >> 2, tig = lane & 3;
    int wm = (warp >> 1) * 64, wn = (warp & 1) * 64;
    int bx = blockIdx.x, by = blockIdx.y;

    // loader: 1 thread/row, 4x CP16 (32 halfs) per matrix
    int r = tid;
    const __half* a_src = A  + (size_t)(by * 128 + r) * K;
    const __half* b_src = Bt + (size_t)(bx * 128 + r) * K;
    uint32_t a_dst = smaddr(&As[0][r * 40]);
    uint32_t b_dst = smaddr(&Bs[0][r * 40]);

    // ldmatrix per-lane byte offsets (relative to stage base)
    uint32_t a_base = smaddr(&As[0][0]);
    uint32_t b_base = smaddr(&Bs[0][0]);
    uint32_t a_lm[4], b_lm[4];
#pragma unroll
    for (int mt = 0; mt < 4; mt++)
        a_lm[mt] = (uint32_t)(((wm + mt * 16 + (lane & 15)) * 40 + (lane >> 4) * 8) * 2);
#pragma unroll
    for (int np = 0; np < 4; np++)
        b_lm[np] = (uint32_t)(((wn + np * 16 + (lane >> 4) * 8 + (lane & 7)) * 40
                               + ((lane >> 3) & 1) * 8) * 2);

    float acc[4][8][4];
#pragma unroll
    for (int i = 0; i < 4; i++)
#pragma unroll
        for (int j = 0; j < 8; j++)
#pragma unroll
            for (int q = 0; q < 4; q++) acc[i][j][q] = 0.f;

    int KT = K >> 5;

#define ISSUE(stage, kt)                                                     \
    {                                                                        \
        const __half* ap = a_src + ((kt) << 5);                              \
        uint32_t ad = a_dst + (stage) * 10240;                               \
        CP16(ad, ap);      CP16(ad + 16, ap + 8);                            \
        CP16(ad + 32, ap + 16); CP16(ad + 48, ap + 24);                      \
        const __half* bp = b_src + ((kt) << 5);                              \
        uint32_t bd = b_dst + (stage) * 10240;                               \
        CP16(bd, bp);      CP16(bd + 16, bp + 8);                            \
        CP16(bd + 32, bp + 16); CP16(bd + 48, bp + 24);                      \
        CP_COMMIT();                                                         \
    }

    ISSUE(0, 0);
    if (KT > 1) ISSUE(1, 1);

    int st = 2, buf = 0;
    for (int kt = 0; kt < KT; kt++) {
        if (kt + 1 < KT) asm volatile("cp.async.wait_group 1;\n");
        else             asm volatile("cp.async.wait_group 0;\n");
        __syncthreads();
        if (kt + 2 < KT) {
            ISSUE(st, kt + 2);
            st = (st == 2) ? 0 : st + 1;
        }

        uint32_t ab = a_base + buf * 10240;
        uint32_t bb = b_base + buf * 10240;
#pragma unroll
        for (int ss = 0; ss < 2; ss++) {
            uint32_t koff = ss * 32;            // 16 halfs
            uint32_t a[4][4], b[8][2];
#pragma unroll
            for (int mt = 0; mt < 4; mt++)
                LDSM4(a[mt][0], a[mt][1], a[mt][2], a[mt][3], ab + a_lm[mt] + koff);
#pragma unroll
            for (int np = 0; np < 4; np++)
                LDSM4(b[2 * np][0], b[2 * np][1], b[2 * np + 1][0], b[2 * np + 1][1],
                      bb + b_lm[np] + koff);
#pragma unroll
            for (int mt = 0; mt < 4; mt++)
#pragma unroll
                for (int nt = 0; nt < 8; nt++) mma16(acc[mt][nt], a[mt], b[nt]);
        }
        buf = (buf == 2) ? 0 : buf + 1;
    }
#undef ISSUE

#pragma unroll
    for (int mt = 0; mt < 4; mt++) {
#pragma unroll
        for (int nt = 0; nt < 8; nt++) {
            int row = by * 128 + wm + mt * 16 + g;
            int col = bx * 128 + wn + nt * 8 + 2 * tig;
            float e[4];
#pragma unroll
            for (int q = 0; q < 4; q++) {
                float c = acc[mt][nt][q];
                if (EPI == 1) c = c / (1.0f + __expf(-c));
                e[q] = c;
            }
            if (sizeof(OT) == 2) {
                __half2* p0 = (__half2*)((__half*)C + (size_t)row * N + col);
                __half2* p1 = (__half2*)((__half*)C + (size_t)(row + 8) * N + col);
                *p0 = __floats2half2_rn(e[0], e[1]);
                *p1 = __floats2half2_rn(e[2], e[3]);
            } else {
                float* p0 = (float*)C + (size_t)row * N + col;
                float* p1 = (float*)C + (size_t)(row + 8) * N + col;
                *(float2*)p0 = make_float2(e[0], e[1]);
                *(float2*)p1 = make_float2(e[2], e[3]);
            }
        }
    }
}

// ---------------------------------------------------------------------------
// FP16 flash attention (R15 + exp2 trick: log2e folded into Q scale).
// ---------------------------------------------------------------------------
__global__ void __launch_bounds__(256, 2) flash_kernel(
    const __half* __restrict__ qkv, __half* __restrict__ ao)
{
    int it = (int)gridDim.x - 1 - (int)blockIdx.x;
    int bh = blockIdx.y;
    int b = bh >> 4, h = bh & 15;
    int i0 = it * 128;

    __shared__ __align__(16) __half smem[2 * 64 * 72 + 2 * 64 * 72];
    __half* Qstage = smem;

    int tid = threadIdx.x, warp = tid >> 5, lane = tid & 31;
    int g = lane >> 2, tig = lane & 3;

    // ---- stage Q, pull to A-frags with (0.125 * log2e) scale ----
    {
        int r = tid >> 1, cb = (tid & 1) * 32;
        const __half* qp = qkv + (size_t)(b * TT + i0 + r) * QS + h * HDD + cb;
        __half* dst = Qstage + r * 72 + cb;
#pragma unroll
        for (int c8 = 0; c8 < 4; c8++)
            *(float4*)(dst + c8 * 8) = *(const float4*)(qp + c8 * 8);
    }
    __syncthreads();
    uint32_t qa[4][4];
    {
        int m = warp * 16 + g;
        __half2 scl = __float2half2_rn(0.125f * 1.44269504f);  // log2-domain
#pragma unroll
        for (int kt = 0; kt < 4; kt++) {
            int kb = kt * 16 + 2 * tig;
            __half2 t0 = *(const __half2*)&Qstage[m * 72 + kb];
            __half2 t1 = *(const __half2*)&Qstage[(m + 8) * 72 + kb];
            __half2 t2 = *(const __half2*)&Qstage[m * 72 + kb + 8];
            __half2 t3 = *(const __half2*)&Qstage[(m + 8) * 72 + kb + 8];
            t0 = __hmul2(t0, scl); t1 = __hmul2(t1, scl);
            t2 = __hmul2(t2, scl); t3 = __hmul2(t3, scl);
            qa[kt][0] = *(uint32_t*)&t0; qa[kt][1] = *(uint32_t*)&t1;
            qa[kt][2] = *(uint32_t*)&t2; qa[kt][3] = *(uint32_t*)&t3;
        }
    }
    __syncthreads();

    int lr = tid >> 2, lc = (tid & 3) * 16;
    const __half* krow = qkv + (size_t)(b * TT + lr) * QS + DD + h * HDD + lc;
    const __half* vrow = qkv + (size_t)(b * TT + lr) * QS + 2 * DD + h * HDD + lc;
    uint32_t kd[2] = { smaddr(smem + lr * 72 + lc),
                       smaddr(smem + 4608 + lr * 72 + lc) };
    uint32_t vd[2] = { smaddr(smem + 9216 + lr * 72 + lc),
                       smaddr(smem + 13824 + lr * 72 + lc) };

    uint32_t k_lm[4];
#pragma unroll
    for (int np = 0; np < 4; np++)
        k_lm[np] = (uint32_t)(((np * 16 + (lane >> 4) * 8 + (lane & 7)) * 72
                               + ((lane >> 3) & 1) * 8) * 2);

    int jt_max = 2 * it + 1;

    {
#pragma unroll
        for (int c = 0; c < 2; c++) {
            CP16(kd[0] + c * 16, krow + c * 8);
            CP16(vd[0] + c * 16, vrow + c * 8);
        }
        CP_COMMIT();
    }

    float o[8][4];
#pragma unroll
    for (int nt = 0; nt < 8; nt++)
#pragma unroll
        for (int r = 0; r < 4; r++) o[nt][r] = 0.f;
    float rm0 = -1e30f, rm1 = -1e30f, rs0 = 0.f, rs1 = 0.f;

    int warp_row0 = i0 + warp * 16;
    int lmat = lane >> 3;
    int lrow = (lane & 7) + 8 * (lmat & 1);
    int lcol8 = 8 * (lmat >> 1);

    for (int jt = 0; jt <= jt_max; jt++) {
        int j0 = jt * 64;
        asm volatile("cp.async.wait_group 0;\n");
        __syncthreads();
        if (jt < jt_max) {
            int jb = (jt + 1) & 1;
            const __half* kp = krow + (size_t)(j0 + 64) * QS;
            const __half* vp = vrow + (size_t)(j0 + 64) * QS;
#pragma unroll
            for (int c = 0; c < 2; c++) {
                CP16(kd[jb] + c * 16, kp + c * 8);
                CP16(vd[jb] + c * 16, vp + c * 8);
            }
            CP_COMMIT();
        }

        if (j0 <= warp_row0 + 15) {
            uint32_t ksb = smaddr(smem) + (jt & 1) * 9216;
            uint32_t vsb = smaddr(smem) + 18432 + (jt & 1) * 9216;
            // ---- S = Q K^T (log2 domain) ----
            float s[8][4];
#pragma unroll
            for (int nt = 0; nt < 8; nt++)
#pragma unroll
                for (int r = 0; r < 4; r++) s[nt][r] = 0.f;
#pragma unroll
            for (int kt = 0; kt < 4; kt++) {
                uint32_t koff = kt * 32;
#pragma unroll
                for (int np = 0; np < 4; np++) {
                    uint32_t b0, b1, b2, b3;
                    LDSM4(b0, b1, b2, b3, ksb + k_lm[np] + koff);
                    uint32_t bb0[2] = { b0, b1 };
                    uint32_t bb1[2] = { b2, b3 };
                    mma16(s[2 * np],     qa[kt], bb0);
                    mma16(s[2 * np + 1], qa[kt], bb1);
                }
            }
            // ---- causal mask ----
            int r0 = warp_row0 + g, r1 = r0 + 8;
            if (j0 + 63 > warp_row0) {
#pragma unroll
                for (int nt = 0; nt < 8; nt++) {
                    int j = j0 + nt * 8 + 2 * tig;
                    if (j     > r0) s[nt][0] = -1e30f;
                    if (j + 1 > r0) s[nt][1] = -1e30f;
                    if (j     > r1) s[nt][2] = -1e30f;
                    if (j + 1 > r1) s[nt][3] = -1e30f;
                }
            }
            // ---- online softmax (exp2) ----
            float m0 = -1e30f, m1 = -1e30f;
#pragma unroll
            for (int nt = 0; nt < 8; nt++) {
                m0 = fmaxf(m0, fmaxf(s[nt][0], s[nt][1]));
                m1 = fmaxf(m1, fmaxf(s[nt][2], s[nt][3]));
            }
            m0 = fmaxf(m0, __shfl_xor_sync(0xffffffffu, m0, 1));
            m0 = fmaxf(m0, __shfl_xor_sync(0xffffffffu, m0, 2));
            m1 = fmaxf(m1, __shfl_xor_sync(0xffffffffu, m1, 1));
            m1 = fmaxf(m1, __shfl_xor_sync(0xffffffffu, m1, 2));
            float nm0 = fmaxf(rm0, m0), nm1 = fmaxf(rm1, m1);
            float al0 = exp2f(rm0 - nm0), al1 = exp2f(rm1 - nm1);
            rm0 = nm0; rm1 = nm1;
            float l0 = 0.f, l1 = 0.f;
#pragma unroll
            for (int nt = 0; nt < 8; nt++) {
                s[nt][0] = exp2f(s[nt][0] - nm0);
                s[nt][1] = exp2f(s[nt][1] - nm0);
                s[nt][2] = exp2f(s[nt][2] - nm1);
                s[nt][3] = exp2f(s[nt][3] - nm1);
                l0 += s[nt][0] + s[nt][1];
                l1 += s[nt][2] + s[nt][3];
            }
            l0 += __shfl_xor_sync(0xffffffffu, l0, 1);
            l0 += __shfl_xor_sync(0xffffffffu, l0, 2);
            l1 += __shfl_xor_sync(0xffffffffu, l1, 1);
            l1 += __shfl_xor_sync(0xffffffffu, l1, 2);
            rs0 = rs0 * al0 + l0;
            rs1 = rs1 * al1 + l1;
#pragma unroll
            for (int nt = 0; nt < 8; nt++) {
                o[nt][0] *= al0; o[nt][1] *= al0;
                o[nt][2] *= al1; o[nt][3] *= al1;
            }
            // ---- O += P V ----
#pragma unroll
            for (int kc = 0; kc < 4; kc++) {
                uint32_t a[4];
                a[0] = packh2(s[2 * kc][0],     s[2 * kc][1]);
                a[1] = packh2(s[2 * kc][2],     s[2 * kc][3]);
                a[2] = packh2(s[2 * kc + 1][0], s[2 * kc + 1][1]);
                a[3] = packh2(s[2 * kc + 1][2], s[2 * kc + 1][3]);
                uint32_t rbase = vsb + (uint32_t)(kc * 16 + lrow) * 144u;
#pragma unroll
                for (int np = 0; np < 4; np++) {
                    uint32_t vaddr = rbase + (uint32_t)(np * 16 + lcol8) * 2u;
                    uint32_t b0, b1, b2, b3;
                    LDSM4T(b0, b1, b2, b3, vaddr);
                    uint32_t bb0[2] = { b0, b1 };
                    uint32_t bb1[2] = { b2, b3 };
                    mma16(o[np * 2],     a, bb0);
                    mma16(o[np * 2 + 1], a, bb1);
                }
            }
        }
    }

    float inv0 = 1.0f / rs0, inv1 = 1.0f / rs1;
    int r0 = i0 + warp * 16 + g;
#pragma unroll
    for (int nt = 0; nt < 8; nt++) {
        int col = h * HDD + nt * 8 + 2 * tig;
        __half2* p0 = (__half2*)(ao + (size_t)(b * TT + r0) * DD + col);
        __half2* p1 = (__half2*)(ao + (size_t)(b * TT + r0 + 8) * DD + col);
        *p0 = __floats2half2_rn(o[nt][0] * inv0, o[nt][1] * inv0);
        *p1 = __floats2half2_rn(o[nt][2] * inv1, o[nt][3] * inv1);
    }
}

// ---------------------------------------------------------------------------
// Launch
// ---------------------------------------------------------------------------
extern "C" void kernel_launch(void* const* d_in, const int* in_sizes, int n_in,
                              void* d_out, int out_size)
{
    const float* x      = (const float*)d_in[0];
    const float* w_pre  = (const float*)d_in[1];
    const float* wq     = (const float*)d_in[2];
    const float* wk     = (const float*)d_in[3];
    const float* wv     = (const float*)d_in[4];
    const float* wo     = (const float*)d_in[5];
    const float* w_attn = (const float*)d_in[6];
    const float* w1     = (const float*)d_in[7];
    const float* w2     = (const float*)d_in[8];
    const float* w_ffn  = (const float*)d_in[9];
    float* out = (float*)d_out;

    __half *h_, *qkv_, *ao_, *y_, *mid_, *w_;
    float *tmp_;
    cudaGetSymbolAddress((void**)&h_,   g_h);
    cudaGetSymbolAddress((void**)&qkv_, g_qkv);
    cudaGetSymbolAddress((void**)&ao_,  g_ao);
    cudaGetSymbolAddress((void**)&tmp_, g_tmp);
    cudaGetSymbolAddress((void**)&y_,   g_y);
    cudaGetSymbolAddress((void**)&mid_, g_mid);
    cudaGetSymbolAddress((void**)&w_,   g_w);

    // 0) pack + transpose + round weights to fp16
    packT_kernel<<<12288, 256>>>(wq, wk, wv, wo, w1, w2, w_);

    // 1) h = rmsnorm(x) -> fp16
    rmsnorm_kernel<float, __half><<<MT, 256>>>(x, nullptr, w_pre, h_);

    // 2) fused qkv projection -> fp16
    {
        dim3 g(QS / 128, MT / 128);
        hgemm_kernel<0, __half><<<g, 128>>>(h_, w_ + WQKV_OFF, qkv_, MT, QS, DD);
    }

    // 3) fp16 flash attention -> ao fp16
    {
        dim3 g(TT / 128, BB * HH);
        flash_kernel<<<g, 256>>>(qkv_, ao_);
    }

    // 4) o-proj (fp32 out) + residual norm -> y fp16
    {
        dim3 g(DD / 128, MT / 128);
        hgemm_kernel<0, float><<<g, 128>>>(ao_, w_ + WO_OFF, tmp_, MT, DD, DD);
    }
    rmsnorm_kernel<__half, __half><<<MT, 256>>>(h_, tmp_, w_attn, y_);

    // 5) FFN
    {
        dim3 g(FFD / 128, MT / 128);
        hgemm_kernel<1, __half><<<g, 128>>>(y_, w_ + W1_OFF, mid_, MT, FFD, DD);
    }
    {
        dim3 g(DD / 128, MT / 128);
        hgemm_kernel<0, float><<<g, 128>>>(mid_, w_ + W2_OFF, tmp_, MT, DD, FFD);
    }
    rmsnorm_kernel<__half, float><<<MT, 256>>>(y_, tmp_, w_ffn, out);
}

// round 17
// speedup vs baseline: 1.1584x; 1.1584x over previous
#include <cuda_runtime.h>
#include <cuda_fp16.h>
#include <cstdint>
#include <cstddef>

#define BB   2
#define TT   2048
#define DD   1024
#define HH   16
#define HDD  64
#define FFD  4096
#define MT   (BB*TT)
#define QS   (3*DD)          // fused qkv row stride (fp16)

// ---------------------------------------------------------------------------
// Scratch
// ---------------------------------------------------------------------------
__device__ __half g_h  [MT*DD];
__device__ __half g_qkv[MT*QS];
__device__ __half g_ao [MT*DD];
__device__ float  g_tmp[MT*DD];
__device__ __half g_y  [MT*DD];
__device__ __half g_mid[MT*FFD];
__device__ __half g_w  [12*1024*1024]; // fp16 T: wqkvT[3072][1024] | woT | w1T | w2T

#define WQKV_OFF 0
#define WO_OFF (3*1024*1024)
#define W1_OFF (4*1024*1024)
#define W2_OFF (8*1024*1024)

// ---------------------------------------------------------------------------
// Helpers
// ---------------------------------------------------------------------------
__device__ __forceinline__ uint32_t smaddr(const void* p) {
    return (uint32_t)__cvta_generic_to_shared(p);
}
#define CP16(dst, src) asm volatile("cp.async.cg.shared.global [%0], [%1], 16;\n" :: "r"(dst), "l"(src))
#define CP_COMMIT()    asm volatile("cp.async.commit_group;\n")

// fp16 m16n8k16
__device__ __forceinline__ void mma16(float* d, const uint32_t* a, const uint32_t* b) {
    asm volatile(
        "mma.sync.aligned.m16n8k16.row.col.f32.f16.f16.f32 "
        "{%0,%1,%2,%3}, {%4,%5,%6,%7}, {%8,%9}, {%0,%1,%2,%3};\n"
        : "+f"(d[0]), "+f"(d[1]), "+f"(d[2]), "+f"(d[3])
        : "r"(a[0]), "r"(a[1]), "r"(a[2]), "r"(a[3]), "r"(b[0]), "r"(b[1]));
}

__device__ __forceinline__ uint32_t packh2(float x, float y) {
    __half2 t = __floats2half2_rn(x, y);
    return *(uint32_t*)&t;
}

#define LDSM4(r0, r1, r2, r3, addr) \
    asm volatile("ldmatrix.sync.aligned.m8n8.x4.shared.b16 {%0,%1,%2,%3}, [%4];" \
                 : "=r"(r0), "=r"(r1), "=r"(r2), "=r"(r3) : "r"(addr))
#define LDSM4T(r0, r1, r2, r3, addr) \
    asm volatile("ldmatrix.sync.aligned.m8n8.x4.trans.shared.b16 {%0,%1,%2,%3}, [%4];" \
                 : "=r"(r0), "=r"(r1), "=r"(r2), "=r"(r3) : "r"(addr))

// ---------------------------------------------------------------------------
// Pack weights -> fp16, TRANSPOSED to [N][K] row-major.  base_t selects the
// global tile index so the pack can be split across two launches:
//   tiles [0,3072)      = wqkvT          (needed before the QKV GEMM)
//   tiles [3072,12288)  = woT, w1T, w2T  (needed from the O-projection on)
// ---------------------------------------------------------------------------
__global__ void __launch_bounds__(256) packT_kernel(
    const float* __restrict__ wq, const float* __restrict__ wk,
    const float* __restrict__ wv, const float* __restrict__ wo,
    const float* __restrict__ w1, const float* __restrict__ w2,
    __half* __restrict__ out, int base_t)
{
    __shared__ float tile[32][33];
    int t = blockIdx.x + base_t;
    const float* src; __half* dst;
    int srcN, dstK, n0, k0, scol;
    if (t < 3072) {
        int nt = t >> 5, kt = t & 31;
        n0 = nt * 32; k0 = kt * 32;
        int sel = n0 >> 10;
        src = sel == 0 ? wq : (sel == 1 ? wk : wv);
        srcN = 1024; scol = n0 & 1023;
        dst = out + WQKV_OFF; dstK = 1024;
    } else if (t < 4096) {
        int u = t - 3072;
        int nt = u >> 5, kt = u & 31;
        n0 = nt * 32; k0 = kt * 32;
        src = wo; srcN = 1024; scol = n0;
        dst = out + WO_OFF; dstK = 1024;
    } else if (t < 8192) {
        int u = t - 4096;
        int nt = u >> 5, kt = u & 31;
        n0 = nt * 32; k0 = kt * 32;
        src = w1; srcN = 4096; scol = n0;
        dst = out + W1_OFF; dstK = 1024;
    } else {
        int u = t - 8192;
        int nt = u >> 7, kt = u & 127;
        n0 = nt * 32; k0 = kt * 32;
        src = w2; srcN = 1024; scol = n0;
        dst = out + W2_OFF; dstK = 4096;
    }
    int tx = threadIdx.x & 31, ty = threadIdx.x >> 5;
#pragma unroll
    for (int i = 0; i < 4; i++)
        tile[ty + i * 8][tx] = src[(size_t)(k0 + ty + i * 8) * srcN + scol + tx];
    __syncthreads();
#pragma unroll
    for (int i = 0; i < 4; i++)
        dst[(size_t)(n0 + ty + i * 8) * dstK + k0 + tx] = __float2half(tile[tx][ty + i * 8]);
}

// ---------------------------------------------------------------------------
// RMSNorm
// ---------------------------------------------------------------------------
template <typename AT, typename OT>
__global__ void __launch_bounds__(256) rmsnorm_kernel(
    const AT* __restrict__ a, const float* __restrict__ b,
    const float* __restrict__ w, OT* __restrict__ out)
{
    int row = blockIdx.x;
    size_t base = (size_t)row * DD;
    float v[4];
    float ss = 0.f;
#pragma unroll
    for (int t = 0; t < 4; t++) {
        int c = threadIdx.x + t * 256;
        float x = (float)a[base + c];
        if (b) x += b[base + c];
        v[t] = x;
        ss += x * x;
    }
    __shared__ float red[8];
#pragma unroll
    for (int o = 16; o; o >>= 1) ss += __shfl_xor_sync(0xffffffffu, ss, o);
    if ((threadIdx.x & 31) == 0) red[threadIdx.x >> 5] = ss;
    __syncthreads();
    if (threadIdx.x == 0) {
        float tot = 0.f;
#pragma unroll
        for (int i = 0; i < 8; i++) tot += red[i];
        red[0] = tot;
    }
    __syncthreads();
    float scale = rsqrtf(red[0] * (1.0f / DD) + 1e-6f);
#pragma unroll
    for (int t = 0; t < 4; t++) {
        int c = threadIdx.x + t * 256;
        out[base + c] = (OT)(v[t] * scale * w[c]);
    }
}

// ---------------------------------------------------------------------------
// FP16 GEMM (R15-proven): BM=BN=128, BK=32, 256 thr (8 warps x 64x32),
// m16n8k16 + LDSM frag loads, 3-stage cp.async, ONE sync/chunk.
// ---------------------------------------------------------------------------
template <int EPI, typename OT>
__global__ void __launch_bounds__(256, 2) hgemm_kernel(
    const __half* __restrict__ A, const __half* __restrict__ Bt,
    OT* __restrict__ C, int M, int N, int K)
{
    __shared__ __half As[3][128 * 40];   // 10240B/stage
    __shared__ __half Bs[3][128 * 40];

    int tid = threadIdx.x;
    int warp = tid >> 5, lane = tid & 31;
    int g = lane >> 2, tig = lane & 3;
    int wm = (warp >> 2) * 64, wn = (warp & 3) * 32;
    int bx = blockIdx.x, by = blockIdx.y;

    int r = tid >> 1, hf = tid & 1;
    const __half* a_src = A  + (size_t)(by * 128 + r) * K + hf * 16;
    const __half* b_src = Bt + (size_t)(bx * 128 + r) * K + hf * 16;
    uint32_t a_dst = smaddr(&As[0][r * 40 + hf * 16]);
    uint32_t b_dst = smaddr(&Bs[0][r * 40 + hf * 16]);

    uint32_t a_base = smaddr(&As[0][0]);
    uint32_t b_base = smaddr(&Bs[0][0]);
    uint32_t a_lm[4], b_lm[2];
#pragma unroll
    for (int mt = 0; mt < 4; mt++)
        a_lm[mt] = (uint32_t)(((wm + mt * 16 + (lane & 15)) * 40 + (lane >> 4) * 8) * 2);
#pragma unroll
    for (int np = 0; np < 2; np++)
        b_lm[np] = (uint32_t)(((wn + np * 16 + (lane >> 4) * 8 + (lane & 7)) * 40
                               + ((lane >> 3) & 1) * 8) * 2);

    float acc[4][4][4];
#pragma unroll
    for (int i = 0; i < 4; i++)
#pragma unroll
        for (int j = 0; j < 4; j++)
#pragma unroll
            for (int q = 0; q < 4; q++) acc[i][j][q] = 0.f;

    int KT = K >> 5;

#define ISSUE(stage, kt)                                                     \
    {                                                                        \
        const __half* ap = a_src + ((kt) << 5);                              \
        uint32_t ad = a_dst + (stage) * 10240;                               \
        CP16(ad, ap); CP16(ad + 16, ap + 8);                                 \
        const __half* bp = b_src + ((kt) << 5);                              \
        uint32_t bd = b_dst + (stage) * 10240;                               \
        CP16(bd, bp); CP16(bd + 16, bp + 8);                                 \
        CP_COMMIT();                                                         \
    }

    ISSUE(0, 0);
    if (KT > 1) ISSUE(1, 1);

    int st = 2, buf = 0;
    for (int kt = 0; kt < KT; kt++) {
        if (kt + 1 < KT) asm volatile("cp.async.wait_group 1;\n");
        else             asm volatile("cp.async.wait_group 0;\n");
        __syncthreads();
        if (kt + 2 < KT) {
            ISSUE(st, kt + 2);
            st = (st == 2) ? 0 : st + 1;
        }

        uint32_t ab = a_base + buf * 10240;
        uint32_t bb = b_base + buf * 10240;
#pragma unroll
        for (int ss = 0; ss < 2; ss++) {
            uint32_t koff = ss * 32;            // 16 halfs
            uint32_t a[4][4], b[4][2];
#pragma unroll
            for (int mt = 0; mt < 4; mt++)
                LDSM4(a[mt][0], a[mt][1], a[mt][2], a[mt][3], ab + a_lm[mt] + koff);
#pragma unroll
            for (int np = 0; np < 2; np++)
                LDSM4(b[2 * np][0], b[2 * np][1], b[2 * np + 1][0], b[2 * np + 1][1],
                      bb + b_lm[np] + koff);
#pragma unroll
            for (int mt = 0; mt < 4; mt++)
#pragma unroll
                for (int nt = 0; nt < 4; nt++) mma16(acc[mt][nt], a[mt], b[nt]);
        }
        buf = (buf == 2) ? 0 : buf + 1;
    }
#undef ISSUE

#pragma unroll
    for (int mt = 0; mt < 4; mt++) {
#pragma unroll
        for (int nt = 0; nt < 4; nt++) {
            int row = by * 128 + wm + mt * 16 + g;
            int col = bx * 128 + wn + nt * 8 + 2 * tig;
            float e[4];
#pragma unroll
            for (int q = 0; q < 4; q++) {
                float c = acc[mt][nt][q];
                if (EPI == 1) c = c / (1.0f + __expf(-c));
                e[q] = c;
            }
            if (sizeof(OT) == 2) {
                __half2* p0 = (__half2*)((__half*)C + (size_t)row * N + col);
                __half2* p1 = (__half2*)((__half*)C + (size_t)(row + 8) * N + col);
                *p0 = __floats2half2_rn(e[0], e[1]);
                *p1 = __floats2half2_rn(e[2], e[3]);
            } else {
                float* p0 = (float*)C + (size_t)row * N + col;
                float* p1 = (float*)C + (size_t)(row + 8) * N + col;
                *(float2*)p0 = make_float2(e[0], e[1]);
                *(float2*)p1 = make_float2(e[2], e[3]);
            }
        }
    }
}

// ---------------------------------------------------------------------------
// FP16 flash attention (R15-proven, expf): ldmatrix K-frags, P==A-frag,
// V via ldmatrix.trans; K/V double-buffered, 1 sync/tile, heavy-first.
// ---------------------------------------------------------------------------
__global__ void __launch_bounds__(256, 2) flash_kernel(
    const __half* __restrict__ qkv, __half* __restrict__ ao)
{
    int it = (int)gridDim.x - 1 - (int)blockIdx.x;
    int bh = blockIdx.y;
    int b = bh >> 4, h = bh & 15;
    int i0 = it * 128;

    __shared__ __align__(16) __half smem[2 * 64 * 72 + 2 * 64 * 72];
    __half* Qstage = smem;

    int tid = threadIdx.x, warp = tid >> 5, lane = tid & 31;
    int g = lane >> 2, tig = lane & 3;

    {
        int r = tid >> 1, cb = (tid & 1) * 32;
        const __half* qp = qkv + (size_t)(b * TT + i0 + r) * QS + h * HDD + cb;
        __half* dst = Qstage + r * 72 + cb;
#pragma unroll
        for (int c8 = 0; c8 < 4; c8++)
            *(float4*)(dst + c8 * 8) = *(const float4*)(qp + c8 * 8);
    }
    __syncthreads();
    uint32_t qa[4][4];
    {
        int m = warp * 16 + g;
        __half2 scl = __float2half2_rn(0.125f);
#pragma unroll
        for (int kt = 0; kt < 4; kt++) {
            int kb = kt * 16 + 2 * tig;
            __half2 t0 = *(const __half2*)&Qstage[m * 72 + kb];
            __half2 t1 = *(const __half2*)&Qstage[(m + 8) * 72 + kb];
            __half2 t2 = *(const __half2*)&Qstage[m * 72 + kb + 8];
            __half2 t3 = *(const __half2*)&Qstage[(m + 8) * 72 + kb + 8];
            t0 = __hmul2(t0, scl); t1 = __hmul2(t1, scl);
            t2 = __hmul2(t2, scl); t3 = __hmul2(t3, scl);
            qa[kt][0] = *(uint32_t*)&t0; qa[kt][1] = *(uint32_t*)&t1;
            qa[kt][2] = *(uint32_t*)&t2; qa[kt][3] = *(uint32_t*)&t3;
        }
    }
    __syncthreads();

    int lr = tid >> 2, lc = (tid & 3) * 16;
    const __half* krow = qkv + (size_t)(b * TT + lr) * QS + DD + h * HDD + lc;
    const __half* vrow = qkv + (size_t)(b * TT + lr) * QS + 2 * DD + h * HDD + lc;
    uint32_t kd[2] = { smaddr(smem + lr * 72 + lc),
                       smaddr(smem + 4608 + lr * 72 + lc) };
    uint32_t vd[2] = { smaddr(smem + 9216 + lr * 72 + lc),
                       smaddr(smem + 13824 + lr * 72 + lc) };

    uint32_t k_lm[4];
#pragma unroll
    for (int np = 0; np < 4; np++)
        k_lm[np] = (uint32_t)(((np * 16 + (lane >> 4) * 8 + (lane & 7)) * 72
                               + ((lane >> 3) & 1) * 8) * 2);

    int jt_max = 2 * it + 1;

    {
#pragma unroll
        for (int c = 0; c < 2; c++) {
            CP16(kd[0] + c * 16, krow + c * 8);
            CP16(vd[0] + c * 16, vrow + c * 8);
        }
        CP_COMMIT();
    }

    float o[8][4];
#pragma unroll
    for (int nt = 0; nt < 8; nt++)
#pragma unroll
        for (int r = 0; r < 4; r++) o[nt][r] = 0.f;
    float rm0 = -1e30f, rm1 = -1e30f, rs0 = 0.f, rs1 = 0.f;

    int warp_row0 = i0 + warp * 16;
    int lmat = lane >> 3;
    int lrow = (lane & 7) + 8 * (lmat & 1);
    int lcol8 = 8 * (lmat >> 1);

    for (int jt = 0; jt <= jt_max; jt++) {
        int j0 = jt * 64;
        asm volatile("cp.async.wait_group 0;\n");
        __syncthreads();
        if (jt < jt_max) {
            int jb = (jt + 1) & 1;
            const __half* kp = krow + (size_t)(j0 + 64) * QS;
            const __half* vp = vrow + (size_t)(j0 + 64) * QS;
#pragma unroll
            for (int c = 0; c < 2; c++) {
                CP16(kd[jb] + c * 16, kp + c * 8);
                CP16(vd[jb] + c * 16, vp + c * 8);
            }
            CP_COMMIT();
        }

        if (j0 <= warp_row0 + 15) {
            uint32_t ksb = smaddr(smem) + (jt & 1) * 9216;
            uint32_t vsb = smaddr(smem) + 18432 + (jt & 1) * 9216;
            float s[8][4];
#pragma unroll
            for (int nt = 0; nt < 8; nt++)
#pragma unroll
                for (int r = 0; r < 4; r++) s[nt][r] = 0.f;
#pragma unroll
            for (int kt = 0; kt < 4; kt++) {
                uint32_t koff = kt * 32;
#pragma unroll
                for (int np = 0; np < 4; np++) {
                    uint32_t b0, b1, b2, b3;
                    LDSM4(b0, b1, b2, b3, ksb + k_lm[np] + koff);
                    uint32_t bb0[2] = { b0, b1 };
                    uint32_t bb1[2] = { b2, b3 };
                    mma16(s[2 * np],     qa[kt], bb0);
                    mma16(s[2 * np + 1], qa[kt], bb1);
                }
            }
            int r0 = warp_row0 + g, r1 = r0 + 8;
            if (j0 + 63 > warp_row0) {
#pragma unroll
                for (int nt = 0; nt < 8; nt++) {
                    int j = j0 + nt * 8 + 2 * tig;
                    if (j     > r0) s[nt][0] = -1e30f;
                    if (j + 1 > r0) s[nt][1] = -1e30f;
                    if (j     > r1) s[nt][2] = -1e30f;
                    if (j + 1 > r1) s[nt][3] = -1e30f;
                }
            }
            float m0 = -1e30f, m1 = -1e30f;
#pragma unroll
            for (int nt = 0; nt < 8; nt++) {
                m0 = fmaxf(m0, fmaxf(s[nt][0], s[nt][1]));
                m1 = fmaxf(m1, fmaxf(s[nt][2], s[nt][3]));
            }
            m0 = fmaxf(m0, __shfl_xor_sync(0xffffffffu, m0, 1));
            m0 = fmaxf(m0, __shfl_xor_sync(0xffffffffu, m0, 2));
            m1 = fmaxf(m1, __shfl_xor_sync(0xffffffffu, m1, 1));
            m1 = fmaxf(m1, __shfl_xor_sync(0xffffffffu, m1, 2));
            float nm0 = fmaxf(rm0, m0), nm1 = fmaxf(rm1, m1);
            float al0 = __expf(rm0 - nm0), al1 = __expf(rm1 - nm1);
            rm0 = nm0; rm1 = nm1;
            float l0 = 0.f, l1 = 0.f;
#pragma unroll
            for (int nt = 0; nt < 8; nt++) {
                s[nt][0] = __expf(s[nt][0] - nm0);
                s[nt][1] = __expf(s[nt][1] - nm0);
                s[nt][2] = __expf(s[nt][2] - nm1);
                s[nt][3] = __expf(s[nt][3] - nm1);
                l0 += s[nt][0] + s[nt][1];
                l1 += s[nt][2] + s[nt][3];
            }
            l0 += __shfl_xor_sync(0xffffffffu, l0, 1);
            l0 += __shfl_xor_sync(0xffffffffu, l0, 2);
            l1 += __shfl_xor_sync(0xffffffffu, l1, 1);
            l1 += __shfl_xor_sync(0xffffffffu, l1, 2);
            rs0 = rs0 * al0 + l0;
            rs1 = rs1 * al1 + l1;
#pragma unroll
            for (int nt = 0; nt < 8; nt++) {
                o[nt][0] *= al0; o[nt][1] *= al0;
                o[nt][2] *= al1; o[nt][3] *= al1;
            }
#pragma unroll
            for (int kc = 0; kc < 4; kc++) {
                uint32_t a[4];
                a[0] = packh2(s[2 * kc][0],     s[2 * kc][1]);
                a[1] = packh2(s[2 * kc][2],     s[2 * kc][3]);
                a[2] = packh2(s[2 * kc + 1][0], s[2 * kc + 1][1]);
                a[3] = packh2(s[2 * kc + 1][2], s[2 * kc + 1][3]);
                uint32_t rbase = vsb + (uint32_t)(kc * 16 + lrow) * 144u;
#pragma unroll
                for (int np = 0; np < 4; np++) {
                    uint32_t vaddr = rbase + (uint32_t)(np * 16 + lcol8) * 2u;
                    uint32_t b0, b1, b2, b3;
                    LDSM4T(b0, b1, b2, b3, vaddr);
                    uint32_t bb0[2] = { b0, b1 };
                    uint32_t bb1[2] = { b2, b3 };
                    mma16(o[np * 2],     a, bb0);
                    mma16(o[np * 2 + 1], a, bb1);
                }
            }
        }
    }

    float inv0 = 1.0f / rs0, inv1 = 1.0f / rs1;
    int r0 = i0 + warp * 16 + g;
#pragma unroll
    for (int nt = 0; nt < 8; nt++) {
        int col = h * HDD + nt * 8 + 2 * tig;
        __half2* p0 = (__half2*)(ao + (size_t)(b * TT + r0) * DD + col);
        __half2* p1 = (__half2*)(ao + (size_t)(b * TT + r0 + 8) * DD + col);
        *p0 = __floats2half2_rn(o[nt][0] * inv0, o[nt][1] * inv0);
        *p1 = __floats2half2_rn(o[nt][2] * inv1, o[nt][3] * inv1);
    }
}

// ---------------------------------------------------------------------------
// Launch: fork-join streams — pack runs on a side stream, overlapped with
// rmsnorm / QKV GEMM / flash on the main (legacy) stream.
// ---------------------------------------------------------------------------
extern "C" void kernel_launch(void* const* d_in, const int* in_sizes, int n_in,
                              void* d_out, int out_size)
{
    const float* x      = (const float*)d_in[0];
    const float* w_pre  = (const float*)d_in[1];
    const float* wq     = (const float*)d_in[2];
    const float* wk     = (const float*)d_in[3];
    const float* wv     = (const float*)d_in[4];
    const float* wo     = (const float*)d_in[5];
    const float* w_attn = (const float*)d_in[6];
    const float* w1     = (const float*)d_in[7];
    const float* w2     = (const float*)d_in[8];
    const float* w_ffn  = (const float*)d_in[9];
    float* out = (float*)d_out;

    __half *h_, *qkv_, *ao_, *y_, *mid_, *w_;
    float *tmp_;
    cudaGetSymbolAddress((void**)&h_,   g_h);
    cudaGetSymbolAddress((void**)&qkv_, g_qkv);
    cudaGetSymbolAddress((void**)&ao_,  g_ao);
    cudaGetSymbolAddress((void**)&tmp_, g_tmp);
    cudaGetSymbolAddress((void**)&y_,   g_y);
    cudaGetSymbolAddress((void**)&mid_, g_mid);
    cudaGetSymbolAddress((void**)&w_,   g_w);

    cudaStream_t s2;
    cudaStreamCreateWithFlags(&s2, cudaStreamNonBlocking);
    cudaEvent_t e0, e1, e2;
    cudaEventCreateWithFlags(&e0, cudaEventDisableTiming);
    cudaEventCreateWithFlags(&e1, cudaEventDisableTiming);
    cudaEventCreateWithFlags(&e2, cudaEventDisableTiming);

    // fork: side stream packs weights
    cudaEventRecord(e0, 0);
    cudaStreamWaitEvent(s2, e0, 0);
    packT_kernel<<<3072, 256, 0, s2>>>(wq, wk, wv, wo, w1, w2, w_, 0);      // qkv
    cudaEventRecord(e1, s2);
    packT_kernel<<<9216, 256, 0, s2>>>(wq, wk, wv, wo, w1, w2, w_, 3072);   // rest
    cudaEventRecord(e2, s2);

    // main: 1) h = rmsnorm(x) -> fp16 (independent of pack)
    rmsnorm_kernel<float, __half><<<MT, 256>>>(x, nullptr, w_pre, h_);

    // 2) fused qkv projection -> fp16 (needs qkv pack)
    cudaStreamWaitEvent(0, e1, 0);
    {
        dim3 g(QS / 128, MT / 128);
        hgemm_kernel<0, __half><<<g, 256>>>(h_, w_ + WQKV_OFF, qkv_, MT, QS, DD);
    }

    // 3) fp16 flash attention -> ao fp16
    {
        dim3 g(TT / 128, BB * HH);
        flash_kernel<<<g, 256>>>(qkv_, ao_);
    }

    // join: rest of weights must be packed from here on
    cudaStreamWaitEvent(0, e2, 0);

    // 4) o-proj (fp32 out) + residual norm -> y fp16
    {
        dim3 g(DD / 128, MT / 128);
        hgemm_kernel<0, float><<<g, 256>>>(ao_, w_ + WO_OFF, tmp_, MT, DD, DD);
    }
    rmsnorm_kernel<__half, __half><<<MT, 256>>>(h_, tmp_, w_attn, y_);

    // 5) FFN
    {
        dim3 g(FFD / 128, MT / 128);
        hgemm_kernel<1, __half><<<g, 256>>>(y_, w_ + W1_OFF, mid_, MT, FFD, DD);
    }
    {
        dim3 g(DD / 128, MT / 128);
        hgemm_kernel<0, float><<<g, 256>>>(mid_, w_ + W2_OFF, tmp_, MT, DD, FFD);
    }
    rmsnorm_kernel<__half, float><<<MT, 256>>>(y_, tmp_, w_ffn, out);

    cudaEventDestroy(e0);
    cudaEventDestroy(e1);
    cudaEventDestroy(e2);
    cudaStreamDestroy(s2);
}